// round 14
// baseline (speedup 1.0000x reference)
#include <cuda_runtime.h>
#include <cuda_bf16.h>
#include <cstdint>

// Problem constants
#define BSZ    4
#define NSEQ   1024
#define DMODEL 1024
#define NHEAD  16
#define DHEAD  64
#define FFDIM  4096
#define MROWS  (BSZ * NSEQ)   // 4096

// ---------------------------------------------------------------------------
// Scratch (device globals; no dynamic allocation allowed)
// ---------------------------------------------------------------------------
__device__ float g_h  [(size_t)MROWS * DMODEL];         // LN1 bf16 alias / LN2 fp32
__device__ float g_v  [(size_t)MROWS * DMODEL];         // V^T bf16 alias
__device__ __nv_bfloat16 g_qk[(size_t)MROWS * 2 * DMODEL];
__device__ __nv_bfloat16 g_S[4ULL * 16 * 1024 * 1024];  // 128 MB scores/probs
__device__ float g_o  [(size_t)MROWS * DMODEL];         // attn out, bf16 alias
__device__ float g_ff [(size_t)MROWS * FFDIM];
__device__ float g_wq [3 * DMODEL * DMODEL];            // qkv weights bf16 alias
__device__ float g_wo [DMODEL * DMODEL];                // out_w bf16 alias
__device__ float g_wf1[(size_t)FFDIM * DMODEL];         // tf32-rounded
__device__ float g_wf2[(size_t)FFDIM * DMODEL];         // tf32-rounded

// ---------------------------------------------------------------------------
// Helpers
// ---------------------------------------------------------------------------
__device__ __forceinline__ float tf32r(float x) {
    unsigned u;
    asm("cvt.rna.tf32.f32 %0, %1;" : "=r"(u) : "f"(x));
    return __uint_as_float(u);
}

__device__ __forceinline__ void cpa16(void* s, const void* g) {
    unsigned sa = (unsigned)__cvta_generic_to_shared(s);
    asm volatile("cp.async.cg.shared.global [%0], [%1], 16;" :: "r"(sa), "l"(g));
}

__device__ __forceinline__ void mma8(float* c, const unsigned* a, const unsigned* b) {
    asm volatile(
        "mma.sync.aligned.m16n8k8.row.col.f32.tf32.tf32.f32 "
        "{%0,%1,%2,%3}, {%4,%5,%6,%7}, {%8,%9}, {%0,%1,%2,%3};"
        : "+f"(c[0]), "+f"(c[1]), "+f"(c[2]), "+f"(c[3])
        : "r"(a[0]), "r"(a[1]), "r"(a[2]), "r"(a[3]), "r"(b[0]), "r"(b[1]));
}

__device__ __forceinline__ void mma16bf(float* c, const unsigned* a, const unsigned* b) {
    asm volatile(
        "mma.sync.aligned.m16n8k16.row.col.f32.bf16.bf16.f32 "
        "{%0,%1,%2,%3}, {%4,%5,%6,%7}, {%8,%9}, {%0,%1,%2,%3};"
        : "+f"(c[0]), "+f"(c[1]), "+f"(c[2]), "+f"(c[3])
        : "r"(a[0]), "r"(a[1]), "r"(a[2]), "r"(a[3]), "r"(b[0]), "r"(b[1]));
}

// gelu, tanh formula via sigmoid identity: 0.5*(1+tanh(u)) == 1/(1+exp(-2u))
__device__ __forceinline__ float gelu_tanh(float x) {
    float x3 = x * x * x;
    float u = 0.7978845608028654f * (x + 0.044715f * x3);
    return x * __fdividef(1.0f, 1.0f + __expf(-2.0f * u));
}

// ---------------------------------------------------------------------------
// Weight prep: qkv,out_w -> bf16; wf1/wf2 -> tf32-rounded. One launch.
// ---------------------------------------------------------------------------
__global__ void prep_w(const float* __restrict__ s0, __nv_bfloat16* __restrict__ d0, int n0,
                       const float* __restrict__ s1, __nv_bfloat16* __restrict__ d1, int n1,
                       const float* __restrict__ s2, float* __restrict__ d2, int n2,
                       const float* __restrict__ s3, float* __restrict__ d3, int n3)
{
    int seg = blockIdx.y;
    if (seg < 2) {
        const float* s = seg ? s1 : s0;
        __nv_bfloat16* d = seg ? d1 : d0;
        int n = seg ? n1 : n0;
        for (int i = blockIdx.x * blockDim.x + threadIdx.x; i < n;
             i += gridDim.x * blockDim.x) {
            float4 v = ((const float4*)s)[i];
            uint2 raw;
            __nv_bfloat162 p0 = __floats2bfloat162_rn(v.x, v.y);
            __nv_bfloat162 p1 = __floats2bfloat162_rn(v.z, v.w);
            raw.x = *(unsigned*)&p0; raw.y = *(unsigned*)&p1;
            ((uint2*)d)[i] = raw;
        }
    } else {
        const float* s = (seg == 2) ? s2 : s3;
        float*       d = (seg == 2) ? d2 : d3;
        int          n = (seg == 2) ? n2 : n3;
        for (int i = blockIdx.x * blockDim.x + threadIdx.x; i < n;
             i += gridDim.x * blockDim.x) {
            float4 v = ((const float4*)s)[i];
            v.x = tf32r(v.x); v.y = tf32r(v.y); v.z = tf32r(v.z); v.w = tf32r(v.w);
            ((float4*)d)[i] = v;
        }
    }
}

// ---------------------------------------------------------------------------
// LayerNorm. OUTBF=1: bf16 output (LN1); OUTBF=0: fp32 tf32-rounded (LN2).
// ---------------------------------------------------------------------------
template <int OUTBF>
__global__ void __launch_bounds__(256) ln_kernel(
    const float* __restrict__ x, const float* __restrict__ w,
    const float* __restrict__ b, void* __restrict__ outp)
{
    int row = blockIdx.x;
    int t = threadIdx.x;
    const float4* xr = (const float4*)(x + (size_t)row * DMODEL);
    float4 v = xr[t];
    float s  = v.x + v.y + v.z + v.w;
    float ss = v.x*v.x + v.y*v.y + v.z*v.z + v.w*v.w;
    #pragma unroll
    for (int o = 16; o; o >>= 1) {
        s  += __shfl_xor_sync(0xffffffffu, s,  o);
        ss += __shfl_xor_sync(0xffffffffu, ss, o);
    }
    __shared__ float rs[8], rss[8];
    int wid = t >> 5, ln = t & 31;
    if (ln == 0) { rs[wid] = s; rss[wid] = ss; }
    __syncthreads();
    if (t < 32) {
        s  = (ln < 8) ? rs[ln]  : 0.f;
        ss = (ln < 8) ? rss[ln] : 0.f;
        #pragma unroll
        for (int o = 4; o; o >>= 1) {
            s  += __shfl_xor_sync(0xffffffffu, s,  o);
            ss += __shfl_xor_sync(0xffffffffu, ss, o);
        }
        if (ln == 0) { rs[0] = s; rss[0] = ss; }
    }
    __syncthreads();
    float mean = rs[0] * (1.0f / DMODEL);
    float var  = rss[0] * (1.0f / DMODEL) - mean * mean;
    float inv  = rsqrtf(var + 1e-5f);
    float4 wv = ((const float4*)w)[t];
    float4 bv = ((const float4*)b)[t];
    float o0 = (v.x - mean) * inv * wv.x + bv.x;
    float o1 = (v.y - mean) * inv * wv.y + bv.y;
    float o2 = (v.z - mean) * inv * wv.z + bv.z;
    float o3 = (v.w - mean) * inv * wv.w + bv.w;
    if (OUTBF) {
        __nv_bfloat16* ob = (__nv_bfloat16*)outp + (size_t)row * DMODEL + t * 4;
        uint2 raw;
        __nv_bfloat162 p0 = __floats2bfloat162_rn(o0, o1);
        __nv_bfloat162 p1 = __floats2bfloat162_rn(o2, o3);
        raw.x = *(unsigned*)&p0; raw.y = *(unsigned*)&p1;
        *(uint2*)ob = raw;
    } else {
        float4 o4;
        o4.x = tf32r(o0); o4.y = tf32r(o1); o4.z = tf32r(o2); o4.w = tf32r(o3);
        ((float4*)((float*)outp + (size_t)row * DMODEL))[t] = o4;
    }
}

// ---------------------------------------------------------------------------
// BF16 qkv GEMM with split epilogue (R11/12-proven).
// ---------------------------------------------------------------------------
__global__ void __launch_bounds__(256, 2) gemm_qkv_bf(
    const __nv_bfloat16* __restrict__ A, const __nv_bfloat16* __restrict__ W,
    const float* __restrict__ bias,
    __nv_bfloat16* __restrict__ qkb, __nv_bfloat16* __restrict__ vt)
{
    constexpr int BM = 128, BK = 64;
    constexpr int SAB = 72;
    constexpr int ASTG = BM * SAB;
    constexpr int MI = 2, NI = 8;
    const int lda = DMODEL, ldb = DMODEL;

    extern __shared__ __nv_bfloat16 smem_b[];
    __nv_bfloat16* As = smem_b;
    __nv_bfloat16* Bs = smem_b + 2 * ASTG;

    int m0 = blockIdx.y * BM;
    int n0 = blockIdx.x * 128;

    int t = threadIdx.x;
    int lane = t & 31, wid = t >> 5;
    int g = lane >> 2, q4 = lane & 3;
    int wm0 = (wid & 3) * 32;
    int wn0 = (wid >> 2) * 64;

    float acc[MI][NI][4];
    #pragma unroll
    for (int mi = 0; mi < MI; mi++)
        #pragma unroll
        for (int ni = 0; ni < NI; ni++)
            #pragma unroll
            for (int rr = 0; rr < 4; rr++) acc[mi][ni][rr] = 0.f;

    const __nv_bfloat16* Abase = A + (size_t)m0 * lda;
    const __nv_bfloat16* Bbase = W + (size_t)n0 * ldb;

    auto issue = [&](int stage, int kt) {
        __nv_bfloat16* Ad = As + stage * ASTG;
        __nv_bfloat16* Bd = Bs + stage * ASTG;
        const __nv_bfloat16* Asrc = Abase + kt * BK;
        const __nv_bfloat16* Bsrc = Bbase + kt * BK;
        #pragma unroll
        for (int i2 = 0; i2 < 4; i2++) {
            int c = i2 * 256 + t;
            int row = c >> 3, ch = (c & 7) * 8;
            cpa16(Ad + row * SAB + ch, Asrc + (size_t)row * lda + ch);
        }
        #pragma unroll
        for (int i2 = 0; i2 < 4; i2++) {
            int c = i2 * 256 + t;
            int row = c >> 3, ch = (c & 7) * 8;
            cpa16(Bd + row * SAB + ch, Bsrc + (size_t)row * ldb + ch);
        }
        asm volatile("cp.async.commit_group;");
    };

    auto compute = [&](int stage) {
        const unsigned* Ag = (const unsigned*)(As + stage * ASTG);
        const unsigned* Bg = (const unsigned*)(Bs + stage * ASTG);
        #pragma unroll
        for (int ks = 0; ks < 4; ks++) {
            unsigned a[MI][4];
            #pragma unroll
            for (int mi = 0; mi < MI; mi++) {
                int row = wm0 + mi * 16 + g;
                const unsigned* p  = Ag + row * 36 + ks * 8 + q4;
                const unsigned* p8 = Ag + (row + 8) * 36 + ks * 8 + q4;
                a[mi][0] = p[0];
                a[mi][1] = p8[0];
                a[mi][2] = p[4];
                a[mi][3] = p8[4];
            }
            unsigned b[NI][2];
            #pragma unroll
            for (int ni = 0; ni < NI; ni++) {
                const unsigned* p = Bg + (wn0 + ni * 8 + g) * 36 + ks * 8 + q4;
                b[ni][0] = p[0];
                b[ni][1] = p[4];
            }
            #pragma unroll
            for (int mi = 0; mi < MI; mi++)
                #pragma unroll
                for (int ni = 0; ni < NI; ni++)
                    mma16bf(acc[mi][ni], a[mi], b[ni]);
        }
    };

    int KT = DMODEL / BK;   // 16
    issue(0, 0);
    for (int kt = 0; kt < KT; kt++) {
        if (kt + 1 < KT) {
            issue((kt + 1) & 1, kt + 1);
            asm volatile("cp.async.wait_group 1;");
        } else {
            asm volatile("cp.async.wait_group 0;");
        }
        __syncthreads();
        compute(kt & 1);
        __syncthreads();
    }

    #pragma unroll
    for (int mi = 0; mi < MI; mi++) {
        int r0 = m0 + wm0 + mi * 16 + g;
        #pragma unroll
        for (int ni = 0; ni < NI; ni++) {
            int cb = n0 + wn0 + ni * 8 + 2 * q4;
            float2 b2 = *(const float2*)(bias + cb);
            float* a4 = acc[mi][ni];
            float v0 = a4[0] + b2.x, v1 = a4[1] + b2.y;
            float v2 = a4[2] + b2.x, v3 = a4[3] + b2.y;
            if (n0 < 2 * DMODEL) {
                *(__nv_bfloat162*)(qkb + (size_t)r0 * (2 * DMODEL) + cb) =
                    __floats2bfloat162_rn(v0, v1);
                *(__nv_bfloat162*)(qkb + (size_t)(r0 + 8) * (2 * DMODEL) + cb) =
                    __floats2bfloat162_rn(v2, v3);
            } else {
                int cv = cb - 2 * DMODEL;
                int b_ = r0 >> 10, i_ = r0 & 1023;
                int h_ = cv >> 6, d_ = cv & 63;
                size_t base = ((size_t)(b_ * 16 + h_) * 64);
                vt[(base + d_)     * NSEQ + i_]     = __float2bfloat16_rn(v0);
                vt[(base + d_ + 1) * NSEQ + i_]     = __float2bfloat16_rn(v1);
                vt[(base + d_)     * NSEQ + i_ + 8] = __float2bfloat16_rn(v2);
                vt[(base + d_ + 1) * NSEQ + i_ + 8] = __float2bfloat16_rn(v3);
            }
        }
    }
}

// ---------------------------------------------------------------------------
// QK^T GEMM (bf16): single K-tile (K=64).
// ---------------------------------------------------------------------------
__global__ void __launch_bounds__(256) gemm_qk(
    const __nv_bfloat16* __restrict__ QK, __nv_bfloat16* __restrict__ S)
{
    constexpr int SAB = 72;
    constexpr int ASTG = 128 * SAB;
    constexpr int LDQ = 2 * DMODEL;
    constexpr int MI = 2, NI = 8;

    extern __shared__ __nv_bfloat16 smem_b[];
    __nv_bfloat16* As = smem_b;
    __nv_bfloat16* Bs = smem_b + ASTG;

    int z = blockIdx.z;
    int bb = z >> 4, hh = z & 15;
    const __nv_bfloat16* Qb = QK + (size_t)bb * NSEQ * LDQ + hh * DHEAD;
    const __nv_bfloat16* Kb = Qb + DMODEL;
    __nv_bfloat16* Sb = S + (size_t)z * NSEQ * NSEQ;

    int m0 = blockIdx.y * 128;
    int n0 = blockIdx.x * 128;

    int t = threadIdx.x;
    int lane = t & 31, wid = t >> 5;
    int g = lane >> 2, q4 = lane & 3;
    int wm0 = (wid & 3) * 32;
    int wn0 = (wid >> 2) * 64;

    #pragma unroll
    for (int i = 0; i < 4; i++) {
        int c = i * 256 + t;
        int row = c >> 3, ch = (c & 7) * 8;
        cpa16(As + row * SAB + ch, Qb + (size_t)(m0 + row) * LDQ + ch);
    }
    #pragma unroll
    for (int i = 0; i < 4; i++) {
        int c = i * 256 + t;
        int row = c >> 3, ch = (c & 7) * 8;
        cpa16(Bs + row * SAB + ch, Kb + (size_t)(n0 + row) * LDQ + ch);
    }
    asm volatile("cp.async.commit_group;");
    asm volatile("cp.async.wait_group 0;");
    __syncthreads();

    float acc[MI][NI][4];
    #pragma unroll
    for (int mi = 0; mi < MI; mi++)
        #pragma unroll
        for (int ni = 0; ni < NI; ni++)
            #pragma unroll
            for (int rr = 0; rr < 4; rr++) acc[mi][ni][rr] = 0.f;

    const unsigned* Ag = (const unsigned*)As;
    const unsigned* Bg = (const unsigned*)Bs;
    #pragma unroll
    for (int ks = 0; ks < 4; ks++) {
        unsigned a[MI][4];
        #pragma unroll
        for (int mi = 0; mi < MI; mi++) {
            int row = wm0 + mi * 16 + g;
            const unsigned* p  = Ag + row * 36 + ks * 8 + q4;
            const unsigned* p8 = Ag + (row + 8) * 36 + ks * 8 + q4;
            a[mi][0] = p[0];
            a[mi][1] = p8[0];
            a[mi][2] = p[4];
            a[mi][3] = p8[4];
        }
        unsigned b[NI][2];
        #pragma unroll
        for (int ni = 0; ni < NI; ni++) {
            const unsigned* p = Bg + (wn0 + ni * 8 + g) * 36 + ks * 8 + q4;
            b[ni][0] = p[0];
            b[ni][1] = p[4];
        }
        #pragma unroll
        for (int mi = 0; mi < MI; mi++)
            #pragma unroll
            for (int ni = 0; ni < NI; ni++)
                mma16bf(acc[mi][ni], a[mi], b[ni]);
    }

    #pragma unroll
    for (int mi = 0; mi < MI; mi++) {
        int r0 = m0 + wm0 + mi * 16 + g;
        #pragma unroll
        for (int ni = 0; ni < NI; ni++) {
            int cb = n0 + wn0 + ni * 8 + 2 * q4;
            float* a4 = acc[mi][ni];
            *(__nv_bfloat162*)(Sb + (size_t)r0 * NSEQ + cb) =
                __floats2bfloat162_rn(a4[0] * 0.125f, a4[1] * 0.125f);
            *(__nv_bfloat162*)(Sb + (size_t)(r0 + 8) * NSEQ + cb) =
                __floats2bfloat162_rn(a4[2] * 0.125f, a4[3] * 0.125f);
        }
    }
}

// ---------------------------------------------------------------------------
// P@V GEMM (bf16): O bf16 head-interleaved [b][i][h*64+d].
// ---------------------------------------------------------------------------
__global__ void __launch_bounds__(256, 2) gemm_pv(
    const __nv_bfloat16* __restrict__ P, const __nv_bfloat16* __restrict__ VT,
    __nv_bfloat16* __restrict__ O)
{
    constexpr int SAB = 72;
    constexpr int ASTG = 128 * SAB;
    constexpr int BSTG = 64 * SAB;
    constexpr int MI = 2, NI = 4;

    extern __shared__ __nv_bfloat16 smem_b[];
    __nv_bfloat16* As = smem_b;
    __nv_bfloat16* Bs = smem_b + 2 * ASTG;

    int z = blockIdx.z;
    int bb = z >> 4, hh = z & 15;
    const __nv_bfloat16* Pb = P + (size_t)z * NSEQ * NSEQ;
    const __nv_bfloat16* Vt = VT + (size_t)z * DHEAD * NSEQ;
    __nv_bfloat16* Ob = O + (size_t)bb * NSEQ * DMODEL + hh * DHEAD;

    int m0 = blockIdx.y * 128;
    int t = threadIdx.x, lane = t & 31, wid = t >> 5;
    int g = lane >> 2, q4 = lane & 3;
    int wm0 = (wid & 3) * 32;
    int wn0 = (wid >> 2) * 32;

    float acc[MI][NI][4];
    #pragma unroll
    for (int mi = 0; mi < MI; mi++)
        #pragma unroll
        for (int ni = 0; ni < NI; ni++)
            #pragma unroll
            for (int rr = 0; rr < 4; rr++) acc[mi][ni][rr] = 0.f;

    auto issue = [&](int s, int kt) {
        __nv_bfloat16* Ad = As + s * ASTG;
        __nv_bfloat16* Bd = Bs + s * BSTG;
        const __nv_bfloat16* Asrc = Pb + kt * 64;
        const __nv_bfloat16* Bsrc = Vt + kt * 64;
        #pragma unroll
        for (int i2 = 0; i2 < 4; i2++) {
            int c = i2 * 256 + t;
            int row = c >> 3, ch = (c & 7) * 8;
            cpa16(Ad + row * SAB + ch, Asrc + (size_t)(m0 + row) * NSEQ + ch);
        }
        #pragma unroll
        for (int i2 = 0; i2 < 2; i2++) {
            int c = i2 * 256 + t;
            int row = c >> 3, ch = (c & 7) * 8;
            cpa16(Bd + row * SAB + ch, Bsrc + (size_t)row * NSEQ + ch);
        }
        asm volatile("cp.async.commit_group;");
    };

    auto compute = [&](int s) {
        const unsigned* Ag = (const unsigned*)(As + s * ASTG);
        const unsigned* Bg = (const unsigned*)(Bs + s * BSTG);
        #pragma unroll
        for (int ks = 0; ks < 4; ks++) {
            unsigned a[MI][4];
            #pragma unroll
            for (int mi = 0; mi < MI; mi++) {
                int row = wm0 + mi * 16 + g;
                const unsigned* p  = Ag + row * 36 + ks * 8 + q4;
                const unsigned* p8 = Ag + (row + 8) * 36 + ks * 8 + q4;
                a[mi][0] = p[0];
                a[mi][1] = p8[0];
                a[mi][2] = p[4];
                a[mi][3] = p8[4];
            }
            unsigned b[NI][2];
            #pragma unroll
            for (int ni = 0; ni < NI; ni++) {
                const unsigned* p = Bg + (wn0 + ni * 8 + g) * 36 + ks * 8 + q4;
                b[ni][0] = p[0];
                b[ni][1] = p[4];
            }
            #pragma unroll
            for (int mi = 0; mi < MI; mi++)
                #pragma unroll
                for (int ni = 0; ni < NI; ni++)
                    mma16bf(acc[mi][ni], a[mi], b[ni]);
        }
    };

    int KT = NSEQ / 64;   // 16
    issue(0, 0);
    for (int kt = 0; kt < KT; kt++) {
        if (kt + 1 < KT) {
            issue((kt + 1) & 1, kt + 1);
            asm volatile("cp.async.wait_group 1;");
        } else {
            asm volatile("cp.async.wait_group 0;");
        }
        __syncthreads();
        compute(kt & 1);
        __syncthreads();
    }

    #pragma unroll
    for (int mi = 0; mi < MI; mi++) {
        int r0 = m0 + wm0 + mi * 16 + g;
        #pragma unroll
        for (int ni = 0; ni < NI; ni++) {
            int cb = wn0 + ni * 8 + 2 * q4;
            float* a4 = acc[mi][ni];
            *(__nv_bfloat162*)(Ob + (size_t)r0 * DMODEL + cb) =
                __floats2bfloat162_rn(a4[0], a4[1]);
            *(__nv_bfloat162*)(Ob + (size_t)(r0 + 8) * DMODEL + cb) =
                __floats2bfloat162_rn(a4[2], a4[3]);
        }
    }
}

// ---------------------------------------------------------------------------
// BF16 out-proj GEMM: out = x + gamma1 * (obuf @ out_w^T + out_b)
//   A = obuf bf16 [4096][1024], W = out_w bf16 [1024][1024].
//   Residual add in exact fp32. Tile 128x128x64, m16n8k16.
// ---------------------------------------------------------------------------
__global__ void __launch_bounds__(256, 2) gemm_obf(
    const __nv_bfloat16* __restrict__ A, const __nv_bfloat16* __restrict__ W,
    const float* __restrict__ bias, float* __restrict__ C,
    const float* __restrict__ res, const float* __restrict__ gamma)
{
    constexpr int BM = 128, BK = 64;
    constexpr int SAB = 72;
    constexpr int ASTG = BM * SAB;
    constexpr int MI = 2, NI = 8;
    const int lda = DMODEL, ldb = DMODEL, ldc = DMODEL;

    extern __shared__ __nv_bfloat16 smem_b[];
    __nv_bfloat16* As = smem_b;
    __nv_bfloat16* Bs = smem_b + 2 * ASTG;

    int m0 = blockIdx.y * BM;
    int n0 = blockIdx.x * 128;

    int t = threadIdx.x;
    int lane = t & 31, wid = t >> 5;
    int g = lane >> 2, q4 = lane & 3;
    int wm0 = (wid & 3) * 32;
    int wn0 = (wid >> 2) * 64;

    float acc[MI][NI][4];
    #pragma unroll
    for (int mi = 0; mi < MI; mi++)
        #pragma unroll
        for (int ni = 0; ni < NI; ni++)
            #pragma unroll
            for (int rr = 0; rr < 4; rr++) acc[mi][ni][rr] = 0.f;

    const __nv_bfloat16* Abase = A + (size_t)m0 * lda;
    const __nv_bfloat16* Bbase = W + (size_t)n0 * ldb;

    auto issue = [&](int stage, int kt) {
        __nv_bfloat16* Ad = As + stage * ASTG;
        __nv_bfloat16* Bd = Bs + stage * ASTG;
        const __nv_bfloat16* Asrc = Abase + kt * BK;
        const __nv_bfloat16* Bsrc = Bbase + kt * BK;
        #pragma unroll
        for (int i2 = 0; i2 < 4; i2++) {
            int c = i2 * 256 + t;
            int row = c >> 3, ch = (c & 7) * 8;
            cpa16(Ad + row * SAB + ch, Asrc + (size_t)row * lda + ch);
        }
        #pragma unroll
        for (int i2 = 0; i2 < 4; i2++) {
            int c = i2 * 256 + t;
            int row = c >> 3, ch = (c & 7) * 8;
            cpa16(Bd + row * SAB + ch, Bsrc + (size_t)row * ldb + ch);
        }
        asm volatile("cp.async.commit_group;");
    };

    auto compute = [&](int stage) {
        const unsigned* Ag = (const unsigned*)(As + stage * ASTG);
        const unsigned* Bg = (const unsigned*)(Bs + stage * ASTG);
        #pragma unroll
        for (int ks = 0; ks < 4; ks++) {
            unsigned a[MI][4];
            #pragma unroll
            for (int mi = 0; mi < MI; mi++) {
                int row = wm0 + mi * 16 + g;
                const unsigned* p  = Ag + row * 36 + ks * 8 + q4;
                const unsigned* p8 = Ag + (row + 8) * 36 + ks * 8 + q4;
                a[mi][0] = p[0];
                a[mi][1] = p8[0];
                a[mi][2] = p[4];
                a[mi][3] = p8[4];
            }
            unsigned b[NI][2];
            #pragma unroll
            for (int ni = 0; ni < NI; ni++) {
                const unsigned* p = Bg + (wn0 + ni * 8 + g) * 36 + ks * 8 + q4;
                b[ni][0] = p[0];
                b[ni][1] = p[4];
            }
            #pragma unroll
            for (int mi = 0; mi < MI; mi++)
                #pragma unroll
                for (int ni = 0; ni < NI; ni++)
                    mma16bf(acc[mi][ni], a[mi], b[ni]);
        }
    };

    int KT = DMODEL / BK;   // 16
    issue(0, 0);
    for (int kt = 0; kt < KT; kt++) {
        if (kt + 1 < KT) {
            issue((kt + 1) & 1, kt + 1);
            asm volatile("cp.async.wait_group 1;");
        } else {
            asm volatile("cp.async.wait_group 0;");
        }
        __syncthreads();
        compute(kt & 1);
        __syncthreads();
    }

    #pragma unroll
    for (int mi = 0; mi < MI; mi++) {
        int r0 = m0 + wm0 + mi * 16 + g;
        #pragma unroll
        for (int ni = 0; ni < NI; ni++) {
            int cb = n0 + wn0 + ni * 8 + 2 * q4;
            float2 b2 = *(const float2*)(bias + cb);
            float2 g2 = *(const float2*)(gamma + cb);
            float* a4 = acc[mi][ni];
            float2 rA = *(const float2*)(res + (size_t)r0 * ldc + cb);
            float2 rB = *(const float2*)(res + (size_t)(r0 + 8) * ldc + cb);
            float v0 = rA.x + g2.x * (a4[0] + b2.x);
            float v1 = rA.y + g2.y * (a4[1] + b2.y);
            float v2 = rB.x + g2.x * (a4[2] + b2.x);
            float v3 = rB.y + g2.y * (a4[3] + b2.y);
            *(float2*)(C + (size_t)r0 * ldc + cb)       = make_float2(v0, v1);
            *(float2*)(C + (size_t)(r0 + 8) * ldc + cb) = make_float2(v2, v3);
        }
    }
}

// ---------------------------------------------------------------------------
// TF32 tensor-core GEMM (FFN): C = epi(A @ W^T + bias)
//   EPI: 2=gelu(+bias)  3=res+gamma*(+bias);  ROUND: tf32-round C.
// ---------------------------------------------------------------------------
template <int EPI, int ROUND>
__global__ void __launch_bounds__(256, 2) gemm_tc(
    const float* __restrict__ A, const float* __restrict__ Bm,
    const float* __restrict__ bias, float* __restrict__ C,
    const float* __restrict__ res, const float* __restrict__ gamma,
    int K, int lda, int ldb, int ldc)
{
    constexpr int BM = 128, BK = 32;
    constexpr int SA  = 36;
    constexpr int ASTG = BM * SA;
    constexpr int MI = 2, NI = 8;

    extern __shared__ float smem_g[];
    float* As = smem_g;
    float* Bs = smem_g + 2 * ASTG;

    int m0 = blockIdx.y * BM;
    int n0 = blockIdx.x * 128;

    int t = threadIdx.x;
    int lane = t & 31, wid = t >> 5;
    int g = lane >> 2, q4 = lane & 3;
    int wm0 = (wid & 3) * 32;
    int wn0 = (wid >> 2) * 64;

    float acc[MI][NI][4];
    #pragma unroll
    for (int mi = 0; mi < MI; mi++)
        #pragma unroll
        for (int ni = 0; ni < NI; ni++)
            #pragma unroll
            for (int rr = 0; rr < 4; rr++) acc[mi][ni][rr] = 0.f;

    const float* Abase = A + (size_t)m0 * lda;
    const float* Bbase = Bm + (size_t)n0 * ldb;

    auto issue = [&](int stage, int kt) {
        float* Ad = As + stage * ASTG;
        float* Bd = Bs + stage * ASTG;
        const float* Asrc = Abase + kt * BK;
        const float* Bsrc = Bbase + kt * BK;
        #pragma unroll
        for (int i2 = 0; i2 < 4; i2++) {
            int c = i2 * 256 + t;
            int row = c >> 3, ch = (c & 7) << 2;
            cpa16(Ad + row * SA + ch, Asrc + (size_t)row * lda + ch);
        }
        #pragma unroll
        for (int i2 = 0; i2 < 4; i2++) {
            int c = i2 * 256 + t;
            int row = c >> 3, ch = (c & 7) << 2;
            cpa16(Bd + row * SA + ch, Bsrc + (size_t)row * ldb + ch);
        }
        asm volatile("cp.async.commit_group;");
    };

    auto compute = [&](int stage) {
        const float* Asg = As + stage * ASTG;
        const float* Bsg = Bs + stage * ASTG;
        #pragma unroll
        for (int ks = 0; ks < 4; ks++) {
            unsigned a[MI][4];
            #pragma unroll
            for (int mi = 0; mi < MI; mi++) {
                const float* p = Asg + (wm0 + mi * 16 + g) * SA + ks * 8 + q4;
                a[mi][0] = __float_as_uint(p[0]);
                a[mi][1] = __float_as_uint(p[8 * SA]);
                a[mi][2] = __float_as_uint(p[4]);
                a[mi][3] = __float_as_uint(p[8 * SA + 4]);
            }
            unsigned b[NI][2];
            #pragma unroll
            for (int ni = 0; ni < NI; ni++) {
                const float* p = Bsg + (wn0 + ni * 8 + g) * SA + ks * 8 + q4;
                b[ni][0] = __float_as_uint(p[0]);
                b[ni][1] = __float_as_uint(p[4]);
            }
            #pragma unroll
            for (int mi = 0; mi < MI; mi++)
                #pragma unroll
                for (int ni = 0; ni < NI; ni++)
                    mma8(acc[mi][ni], a[mi], b[ni]);
        }
    };

    int KT = K / BK;
    issue(0, 0);
    for (int kt = 0; kt < KT; kt++) {
        if (kt + 1 < KT) {
            issue((kt + 1) & 1, kt + 1);
            asm volatile("cp.async.wait_group 1;");
        } else {
            asm volatile("cp.async.wait_group 0;");
        }
        __syncthreads();
        compute(kt & 1);
        __syncthreads();
    }

    #pragma unroll
    for (int mi = 0; mi < MI; mi++) {
        int r0 = m0 + wm0 + mi * 16 + g;
        #pragma unroll
        for (int ni = 0; ni < NI; ni++) {
            int cb = n0 + wn0 + ni * 8 + 2 * q4;
            float2 b2 = *(const float2*)(bias + cb);
            float* a4 = acc[mi][ni];
            float v0 = a4[0] + b2.x, v1 = a4[1] + b2.y;
            float v2 = a4[2] + b2.x, v3 = a4[3] + b2.y;
            if (EPI == 2) {
                v0 = gelu_tanh(v0); v1 = gelu_tanh(v1);
                v2 = gelu_tanh(v2); v3 = gelu_tanh(v3);
            }
            if (EPI == 3) {
                float2 g2 = *(const float2*)(gamma + cb);
                float2 rA = *(const float2*)(res + (size_t)r0 * ldc + cb);
                float2 rB = *(const float2*)(res + (size_t)(r0 + 8) * ldc + cb);
                v0 = rA.x + g2.x * v0; v1 = rA.y + g2.y * v1;
                v2 = rB.x + g2.x * v2; v3 = rB.y + g2.y * v3;
            }
            if (ROUND) {
                v0 = tf32r(v0); v1 = tf32r(v1); v2 = tf32r(v2); v3 = tf32r(v3);
            }
            *(float2*)(C + (size_t)r0 * ldc + cb)       = make_float2(v0, v1);
            *(float2*)(C + (size_t)(r0 + 8) * ldc + cb) = make_float2(v2, v3);
        }
    }
}

// ---------------------------------------------------------------------------
// Fused talking-heads: mix -> softmax -> mix, in place on S (bf16 I/O).
// ---------------------------------------------------------------------------
__global__ void __launch_bounds__(512) attn_mix_softmax(
    const float* __restrict__ wl, const float* __restrict__ bl,
    const float* __restrict__ ww, const float* __restrict__ bw,
    __nv_bfloat16* __restrict__ S)
{
    extern __shared__ float Ssh[];      // [16][1024] fp32
    __shared__ float wls[256], wws[256], bls[16], bws[16];

    int t = threadIdx.x;
    int b = blockIdx.x >> 10;
    int i = blockIdx.x & 1023;

    if (t < 256) { wls[t] = wl[t]; wws[t] = ww[t]; }
    if (t < 16)  { bls[t] = bl[t]; bws[t] = bw[t]; }

    __nv_bfloat16* Sg = S + (size_t)(b * NHEAD) * NSEQ * NSEQ + (size_t)i * NSEQ;
    const long long NN = (long long)NSEQ * NSEQ;

    #pragma unroll
    for (int ii = 0; ii < 4; ii++) {
        int idx = ii * 512 + t;
        int h = idx >> 7, j4 = idx & 127;
        uint4 raw = ((const uint4*)(Sg + (size_t)h * NN))[j4];
        float* dst = Ssh + h * NSEQ + j4 * 8;
        unsigned p0 = raw.x, p1 = raw.y, p2 = raw.z, p3 = raw.w;
        dst[0] = __uint_as_float(p0 << 16); dst[1] = __uint_as_float(p0 & 0xFFFF0000u);
        dst[2] = __uint_as_float(p1 << 16); dst[3] = __uint_as_float(p1 & 0xFFFF0000u);
        dst[4] = __uint_as_float(p2 << 16); dst[5] = __uint_as_float(p2 & 0xFFFF0000u);
        dst[6] = __uint_as_float(p3 << 16); dst[7] = __uint_as_float(p3 & 0xFFFF0000u);
    }
    __syncthreads();

    #pragma unroll
    for (int jj = 0; jj < 2; jj++) {
        int j = t + jj * 512;
        float sv[16];
        #pragma unroll
        for (int h = 0; h < 16; h++) sv[h] = Ssh[h * NSEQ + j];
        #pragma unroll
        for (int gg = 0; gg < 16; gg++) {
            float acc = bls[gg];
            #pragma unroll
            for (int h = 0; h < 16; h++) acc += wls[gg * 16 + h] * sv[h];
            Ssh[gg * NSEQ + j] = acc;
        }
    }
    __syncthreads();

    {
        int w = t >> 5, l = t & 31;
        float* row = Ssh + w * NSEQ;
        float mx = -1e30f;
        for (int m = l; m < NSEQ; m += 32) mx = fmaxf(mx, row[m]);
        #pragma unroll
        for (int o = 16; o; o >>= 1) mx = fmaxf(mx, __shfl_xor_sync(0xffffffffu, mx, o));
        float sum = 0.f;
        for (int m = l; m < NSEQ; m += 32) {
            float e = __expf(row[m] - mx);
            row[m] = e;
            sum += e;
        }
        #pragma unroll
        for (int o = 16; o; o >>= 1) sum += __shfl_xor_sync(0xffffffffu, sum, o);
        float inv = 1.f / sum;
        for (int m = l; m < NSEQ; m += 32) row[m] *= inv;
    }
    __syncthreads();

    #pragma unroll
    for (int jj = 0; jj < 2; jj++) {
        int j = t + jj * 512;
        float pv[16];
        #pragma unroll
        for (int h = 0; h < 16; h++) pv[h] = Ssh[h * NSEQ + j];
        #pragma unroll
        for (int gg = 0; gg < 16; gg++) {
            float acc = bws[gg];
            #pragma unroll
            for (int h = 0; h < 16; h++) acc += wws[gg * 16 + h] * pv[h];
            Ssh[gg * NSEQ + j] = acc;
        }
    }
    __syncthreads();

    #pragma unroll
    for (int ii = 0; ii < 4; ii++) {
        int idx = ii * 512 + t;
        int h = idx >> 7, j4 = idx & 127;
        const float* src = Ssh + h * NSEQ + j4 * 8;
        uint4 raw;
        __nv_bfloat162 h0 = __floats2bfloat162_rn(src[0], src[1]);
        __nv_bfloat162 h1 = __floats2bfloat162_rn(src[2], src[3]);
        __nv_bfloat162 h2 = __floats2bfloat162_rn(src[4], src[5]);
        __nv_bfloat162 h3 = __floats2bfloat162_rn(src[6], src[7]);
        raw.x = *(unsigned*)&h0; raw.y = *(unsigned*)&h1;
        raw.z = *(unsigned*)&h2; raw.w = *(unsigned*)&h3;
        ((uint4*)(Sg + (size_t)h * NN))[j4] = raw;
    }
}

// ---------------------------------------------------------------------------
// Launch
// ---------------------------------------------------------------------------
extern "C" void kernel_launch(void* const* d_in, const int* in_sizes, int n_in,
                              void* d_out, int out_size)
{
    const float* x      = (const float*)d_in[0];
    const float* ln1_w  = (const float*)d_in[1];
    const float* ln1_b  = (const float*)d_in[2];
    const float* qkv_w  = (const float*)d_in[3];
    const float* qkv_b  = (const float*)d_in[4];
    const float* pl_w   = (const float*)d_in[5];
    const float* pl_b   = (const float*)d_in[6];
    const float* pw_w   = (const float*)d_in[7];
    const float* pw_b   = (const float*)d_in[8];
    const float* out_w  = (const float*)d_in[9];
    const float* out_b  = (const float*)d_in[10];
    const float* gamma1 = (const float*)d_in[11];
    const float* ln2_w  = (const float*)d_in[12];
    const float* ln2_b  = (const float*)d_in[13];
    const float* fc1_w  = (const float*)d_in[14];
    const float* fc1_b  = (const float*)d_in[15];
    const float* fc2_w  = (const float*)d_in[16];
    const float* fc2_b  = (const float*)d_in[17];
    const float* gamma2 = (const float*)d_in[18];
    float* out = (float*)d_out;

    float *hbuf, *vbuf, *obuf, *ff, *wq, *wo, *wf1, *wf2;
    __nv_bfloat16 *S, *qk;
    cudaGetSymbolAddress((void**)&hbuf, g_h);
    cudaGetSymbolAddress((void**)&vbuf, g_v);
    cudaGetSymbolAddress((void**)&qk,   g_qk);
    cudaGetSymbolAddress((void**)&S,    g_S);
    cudaGetSymbolAddress((void**)&obuf, g_o);
    cudaGetSymbolAddress((void**)&ff,   g_ff);
    cudaGetSymbolAddress((void**)&wq,   g_wq);
    cudaGetSymbolAddress((void**)&wo,   g_wo);
    cudaGetSymbolAddress((void**)&wf1,  g_wf1);
    cudaGetSymbolAddress((void**)&wf2,  g_wf2);

    __nv_bfloat16* hb  = (__nv_bfloat16*)hbuf;
    __nv_bfloat16* wqb = (__nv_bfloat16*)wq;
    __nv_bfloat16* wob = (__nv_bfloat16*)wo;
    __nv_bfloat16* vt  = (__nv_bfloat16*)vbuf;
    __nv_bfloat16* ob  = (__nv_bfloat16*)obuf;

    const int TC_SMEM  = 4 * 128 * 36 * 4;                 // 73728 B
    const int BF_SMEM  = 4 * 128 * 72 * 2;                 // 73728 B
    const int QK_SMEM  = 2 * 128 * 72 * 2;                 // 36864 B
    const int PV_SMEM  = (2 * 128 * 72 + 2 * 64 * 72) * 2; // 55296 B

    cudaFuncSetAttribute(attn_mix_softmax,
                         cudaFuncAttributeMaxDynamicSharedMemorySize, 65536);
    cudaFuncSetAttribute(gemm_qkv_bf, cudaFuncAttributeMaxDynamicSharedMemorySize, BF_SMEM);
    cudaFuncSetAttribute(gemm_obf, cudaFuncAttributeMaxDynamicSharedMemorySize, BF_SMEM);
    cudaFuncSetAttribute(gemm_qk, cudaFuncAttributeMaxDynamicSharedMemorySize, QK_SMEM);
    cudaFuncSetAttribute(gemm_pv, cudaFuncAttributeMaxDynamicSharedMemorySize, PV_SMEM);
    cudaFuncSetAttribute(gemm_tc<2,1>, cudaFuncAttributeMaxDynamicSharedMemorySize, TC_SMEM);
    cudaFuncSetAttribute(gemm_tc<3,0>, cudaFuncAttributeMaxDynamicSharedMemorySize, TC_SMEM);

    // 0) Weight prep: qkv,out_w -> bf16; wf1/wf2 -> tf32
    prep_w<<<dim3(1024, 4), 256>>>(
        qkv_w, wqb, 3 * DMODEL * DMODEL / 4,
        out_w, wob, DMODEL * DMODEL / 4,
        fc1_w, wf1, FFDIM * DMODEL / 4,
        fc2_w, wf2, FFDIM * DMODEL / 4);

    // 1) LN1 -> bf16
    ln_kernel<1><<<MROWS, 256>>>(x, ln1_w, ln1_b, hb);

    // 2) qkv (bf16), split epilogue: Q,K -> g_qk; V -> V^T bf16
    gemm_qkv_bf<<<dim3(24, 32), 256, BF_SMEM>>>(hb, wqb, qkv_b, qk, vt);

    // 3) S = (Q K^T)/8
    gemm_qk<<<dim3(8, 8, 64), 256, QK_SMEM>>>(qk, S);

    // 4) talking-heads mix -> softmax -> mix
    attn_mix_softmax<<<BSZ * NSEQ, 512, 65536>>>(pl_w, pl_b, pw_w, pw_b, S);

    // 5) O = P2 @ V  (bf16 out)
    gemm_pv<<<dim3(1, 8, 64), 256, PV_SMEM>>>(S, vt, ob);

    // 6) x1 = x + gamma1 * (O @ out_w^T + out_b)   (bf16 GEMM, fp32 residual)
    gemm_obf<<<dim3(8, 32), 256, BF_SMEM>>>(ob, wob, out_b, out, x, gamma1);

    // 7) LN2 -> fp32/tf32
    ln_kernel<0><<<MROWS, 256>>>(out, ln2_w, ln2_b, hbuf);

    // 8) ff = gelu(hbuf @ fc1_w^T + fc1_b)   (tf32)
    gemm_tc<2,1><<<dim3(32, 32), 256, TC_SMEM>>>(
        hbuf, wf1, fc1_b, ff, nullptr, nullptr,
        DMODEL, DMODEL, DMODEL, FFDIM);

    // 9) out = x1 + gamma2 * (ff @ fc2_w^T + fc2_b)   (tf32)
    gemm_tc<3,0><<<dim3(8, 32), 256, TC_SMEM>>>(
        ff, wf2, fc2_b, out, out, gamma2,
        FFDIM, FFDIM, FFDIM, DMODEL);
}

// round 15
// speedup vs baseline: 1.2956x; 1.2956x over previous
#include <cuda_runtime.h>
#include <cuda_bf16.h>
#include <cuda_fp16.h>
#include <cstdint>

// Problem constants
#define BSZ    4
#define NSEQ   1024
#define DMODEL 1024
#define NHEAD  16
#define DHEAD  64
#define FFDIM  4096
#define MROWS  (BSZ * NSEQ)   // 4096

// ---------------------------------------------------------------------------
// Scratch (device globals; no dynamic allocation allowed)
// ---------------------------------------------------------------------------
__device__ float g_h  [(size_t)MROWS * DMODEL];         // LN1 bf16 / LN2 fp16 alias
__device__ float g_v  [(size_t)MROWS * DMODEL];         // V^T bf16 alias
__device__ __nv_bfloat16 g_qk[(size_t)MROWS * 2 * DMODEL];
__device__ __nv_bfloat16 g_S[4ULL * 16 * 1024 * 1024];  // 128 MB scores/probs
__device__ float g_o  [(size_t)MROWS * DMODEL];         // attn out, bf16 alias
__device__ float g_ff [(size_t)MROWS * FFDIM];          // gelu out, fp16 alias
__device__ float g_wq [3 * DMODEL * DMODEL];            // qkv weights bf16 alias
__device__ float g_wo [DMODEL * DMODEL];                // out_w bf16 alias
__device__ float g_wf1[(size_t)FFDIM * DMODEL];         // fc1_w fp16 alias
__device__ float g_wf2[(size_t)FFDIM * DMODEL];         // fc2_w fp16 alias

// ---------------------------------------------------------------------------
// Helpers
// ---------------------------------------------------------------------------
__device__ __forceinline__ void cpa16(void* s, const void* g) {
    unsigned sa = (unsigned)__cvta_generic_to_shared(s);
    asm volatile("cp.async.cg.shared.global [%0], [%1], 16;" :: "r"(sa), "l"(g));
}

__device__ __forceinline__ void mma16bf(float* c, const unsigned* a, const unsigned* b) {
    asm volatile(
        "mma.sync.aligned.m16n8k16.row.col.f32.bf16.bf16.f32 "
        "{%0,%1,%2,%3}, {%4,%5,%6,%7}, {%8,%9}, {%0,%1,%2,%3};"
        : "+f"(c[0]), "+f"(c[1]), "+f"(c[2]), "+f"(c[3])
        : "r"(a[0]), "r"(a[1]), "r"(a[2]), "r"(a[3]), "r"(b[0]), "r"(b[1]));
}

__device__ __forceinline__ void mma16h(float* c, const unsigned* a, const unsigned* b) {
    asm volatile(
        "mma.sync.aligned.m16n8k16.row.col.f32.f16.f16.f32 "
        "{%0,%1,%2,%3}, {%4,%5,%6,%7}, {%8,%9}, {%0,%1,%2,%3};"
        : "+f"(c[0]), "+f"(c[1]), "+f"(c[2]), "+f"(c[3])
        : "r"(a[0]), "r"(a[1]), "r"(a[2]), "r"(a[3]), "r"(b[0]), "r"(b[1]));
}

// gelu (tanh formula) via sigmoid identity: 0.5*(1+tanh(u)) == 1/(1+exp(-2u))
__device__ __forceinline__ float gelu_tanh(float x) {
    float x3 = x * x * x;
    float u = 0.7978845608028654f * (x + 0.044715f * x3);
    return x * __fdividef(1.0f, 1.0f + __expf(-2.0f * u));
}

// ---------------------------------------------------------------------------
// Weight prep: qkv,out_w -> bf16; wf1,wf2 -> fp16. One launch.
// ---------------------------------------------------------------------------
__global__ void prep_w(const float* __restrict__ s0, __nv_bfloat16* __restrict__ d0, int n0,
                       const float* __restrict__ s1, __nv_bfloat16* __restrict__ d1, int n1,
                       const float* __restrict__ s2, __half* __restrict__ d2, int n2,
                       const float* __restrict__ s3, __half* __restrict__ d3, int n3)
{
    int seg = blockIdx.y;
    if (seg < 2) {
        const float* s = seg ? s1 : s0;
        __nv_bfloat16* d = seg ? d1 : d0;
        int n = seg ? n1 : n0;
        for (int i = blockIdx.x * blockDim.x + threadIdx.x; i < n;
             i += gridDim.x * blockDim.x) {
            float4 v = ((const float4*)s)[i];
            uint2 raw;
            __nv_bfloat162 p0 = __floats2bfloat162_rn(v.x, v.y);
            __nv_bfloat162 p1 = __floats2bfloat162_rn(v.z, v.w);
            raw.x = *(unsigned*)&p0; raw.y = *(unsigned*)&p1;
            ((uint2*)d)[i] = raw;
        }
    } else {
        const float* s = (seg == 2) ? s2 : s3;
        __half* d = (seg == 2) ? d2 : d3;
        int n = (seg == 2) ? n2 : n3;
        for (int i = blockIdx.x * blockDim.x + threadIdx.x; i < n;
             i += gridDim.x * blockDim.x) {
            float4 v = ((const float4*)s)[i];
            uint2 raw;
            __half2 p0 = __floats2half2_rn(v.x, v.y);
            __half2 p1 = __floats2half2_rn(v.z, v.w);
            raw.x = *(unsigned*)&p0; raw.y = *(unsigned*)&p1;
            ((uint2*)d)[i] = raw;
        }
    }
}

// ---------------------------------------------------------------------------
// LayerNorm. MODE=1: bf16 out (LN1); MODE=2: fp16 out (LN2).
// ---------------------------------------------------------------------------
template <int MODE>
__global__ void __launch_bounds__(256) ln_kernel(
    const float* __restrict__ x, const float* __restrict__ w,
    const float* __restrict__ b, void* __restrict__ outp)
{
    int row = blockIdx.x;
    int t = threadIdx.x;
    const float4* xr = (const float4*)(x + (size_t)row * DMODEL);
    float4 v = xr[t];
    float s  = v.x + v.y + v.z + v.w;
    float ss = v.x*v.x + v.y*v.y + v.z*v.z + v.w*v.w;
    #pragma unroll
    for (int o = 16; o; o >>= 1) {
        s  += __shfl_xor_sync(0xffffffffu, s,  o);
        ss += __shfl_xor_sync(0xffffffffu, ss, o);
    }
    __shared__ float rs[8], rss[8];
    int wid = t >> 5, ln = t & 31;
    if (ln == 0) { rs[wid] = s; rss[wid] = ss; }
    __syncthreads();
    if (t < 32) {
        s  = (ln < 8) ? rs[ln]  : 0.f;
        ss = (ln < 8) ? rss[ln] : 0.f;
        #pragma unroll
        for (int o = 4; o; o >>= 1) {
            s  += __shfl_xor_sync(0xffffffffu, s,  o);
            ss += __shfl_xor_sync(0xffffffffu, ss, o);
        }
        if (ln == 0) { rs[0] = s; rss[0] = ss; }
    }
    __syncthreads();
    float mean = rs[0] * (1.0f / DMODEL);
    float var  = rss[0] * (1.0f / DMODEL) - mean * mean;
    float inv  = rsqrtf(var + 1e-5f);
    float4 wv = ((const float4*)w)[t];
    float4 bv = ((const float4*)b)[t];
    float o0 = (v.x - mean) * inv * wv.x + bv.x;
    float o1 = (v.y - mean) * inv * wv.y + bv.y;
    float o2 = (v.z - mean) * inv * wv.z + bv.z;
    float o3 = (v.w - mean) * inv * wv.w + bv.w;
    uint2 raw;
    if (MODE == 1) {
        __nv_bfloat162 p0 = __floats2bfloat162_rn(o0, o1);
        __nv_bfloat162 p1 = __floats2bfloat162_rn(o2, o3);
        raw.x = *(unsigned*)&p0; raw.y = *(unsigned*)&p1;
        *(uint2*)((__nv_bfloat16*)outp + (size_t)row * DMODEL + t * 4) = raw;
    } else {
        __half2 p0 = __floats2half2_rn(o0, o1);
        __half2 p1 = __floats2half2_rn(o2, o3);
        raw.x = *(unsigned*)&p0; raw.y = *(unsigned*)&p1;
        *(uint2*)((__half*)outp + (size_t)row * DMODEL + t * 4) = raw;
    }
}

// ---------------------------------------------------------------------------
// BF16 qkv GEMM with split epilogue (proven).
// ---------------------------------------------------------------------------
__global__ void __launch_bounds__(256, 2) gemm_qkv_bf(
    const __nv_bfloat16* __restrict__ A, const __nv_bfloat16* __restrict__ W,
    const float* __restrict__ bias,
    __nv_bfloat16* __restrict__ qkb, __nv_bfloat16* __restrict__ vt)
{
    constexpr int BM = 128, BK = 64;
    constexpr int SAB = 72;
    constexpr int ASTG = BM * SAB;
    constexpr int MI = 2, NI = 8;
    const int lda = DMODEL, ldb = DMODEL;

    extern __shared__ __nv_bfloat16 smem_b[];
    __nv_bfloat16* As = smem_b;
    __nv_bfloat16* Bs = smem_b + 2 * ASTG;

    int m0 = blockIdx.y * BM;
    int n0 = blockIdx.x * 128;

    int t = threadIdx.x;
    int lane = t & 31, wid = t >> 5;
    int g = lane >> 2, q4 = lane & 3;
    int wm0 = (wid & 3) * 32;
    int wn0 = (wid >> 2) * 64;

    float acc[MI][NI][4];
    #pragma unroll
    for (int mi = 0; mi < MI; mi++)
        #pragma unroll
        for (int ni = 0; ni < NI; ni++)
            #pragma unroll
            for (int rr = 0; rr < 4; rr++) acc[mi][ni][rr] = 0.f;

    const __nv_bfloat16* Abase = A + (size_t)m0 * lda;
    const __nv_bfloat16* Bbase = W + (size_t)n0 * ldb;

    auto issue = [&](int stage, int kt) {
        __nv_bfloat16* Ad = As + stage * ASTG;
        __nv_bfloat16* Bd = Bs + stage * ASTG;
        const __nv_bfloat16* Asrc = Abase + kt * BK;
        const __nv_bfloat16* Bsrc = Bbase + kt * BK;
        #pragma unroll
        for (int i2 = 0; i2 < 4; i2++) {
            int c = i2 * 256 + t;
            int row = c >> 3, ch = (c & 7) * 8;
            cpa16(Ad + row * SAB + ch, Asrc + (size_t)row * lda + ch);
        }
        #pragma unroll
        for (int i2 = 0; i2 < 4; i2++) {
            int c = i2 * 256 + t;
            int row = c >> 3, ch = (c & 7) * 8;
            cpa16(Bd + row * SAB + ch, Bsrc + (size_t)row * ldb + ch);
        }
        asm volatile("cp.async.commit_group;");
    };

    auto compute = [&](int stage) {
        const unsigned* Ag = (const unsigned*)(As + stage * ASTG);
        const unsigned* Bg = (const unsigned*)(Bs + stage * ASTG);
        #pragma unroll
        for (int ks = 0; ks < 4; ks++) {
            unsigned a[MI][4];
            #pragma unroll
            for (int mi = 0; mi < MI; mi++) {
                int row = wm0 + mi * 16 + g;
                const unsigned* p  = Ag + row * 36 + ks * 8 + q4;
                const unsigned* p8 = Ag + (row + 8) * 36 + ks * 8 + q4;
                a[mi][0] = p[0];
                a[mi][1] = p8[0];
                a[mi][2] = p[4];
                a[mi][3] = p8[4];
            }
            unsigned b[NI][2];
            #pragma unroll
            for (int ni = 0; ni < NI; ni++) {
                const unsigned* p = Bg + (wn0 + ni * 8 + g) * 36 + ks * 8 + q4;
                b[ni][0] = p[0];
                b[ni][1] = p[4];
            }
            #pragma unroll
            for (int mi = 0; mi < MI; mi++)
                #pragma unroll
                for (int ni = 0; ni < NI; ni++)
                    mma16bf(acc[mi][ni], a[mi], b[ni]);
        }
    };

    int KT = DMODEL / BK;   // 16
    issue(0, 0);
    for (int kt = 0; kt < KT; kt++) {
        if (kt + 1 < KT) {
            issue((kt + 1) & 1, kt + 1);
            asm volatile("cp.async.wait_group 1;");
        } else {
            asm volatile("cp.async.wait_group 0;");
        }
        __syncthreads();
        compute(kt & 1);
        __syncthreads();
    }

    #pragma unroll
    for (int mi = 0; mi < MI; mi++) {
        int r0 = m0 + wm0 + mi * 16 + g;
        #pragma unroll
        for (int ni = 0; ni < NI; ni++) {
            int cb = n0 + wn0 + ni * 8 + 2 * q4;
            float2 b2 = *(const float2*)(bias + cb);
            float* a4 = acc[mi][ni];
            float v0 = a4[0] + b2.x, v1 = a4[1] + b2.y;
            float v2 = a4[2] + b2.x, v3 = a4[3] + b2.y;
            if (n0 < 2 * DMODEL) {
                *(__nv_bfloat162*)(qkb + (size_t)r0 * (2 * DMODEL) + cb) =
                    __floats2bfloat162_rn(v0, v1);
                *(__nv_bfloat162*)(qkb + (size_t)(r0 + 8) * (2 * DMODEL) + cb) =
                    __floats2bfloat162_rn(v2, v3);
            } else {
                int cv = cb - 2 * DMODEL;
                int b_ = r0 >> 10, i_ = r0 & 1023;
                int h_ = cv >> 6, d_ = cv & 63;
                size_t base = ((size_t)(b_ * 16 + h_) * 64);
                vt[(base + d_)     * NSEQ + i_]     = __float2bfloat16_rn(v0);
                vt[(base + d_ + 1) * NSEQ + i_]     = __float2bfloat16_rn(v1);
                vt[(base + d_)     * NSEQ + i_ + 8] = __float2bfloat16_rn(v2);
                vt[(base + d_ + 1) * NSEQ + i_ + 8] = __float2bfloat16_rn(v3);
            }
        }
    }
}

// ---------------------------------------------------------------------------
// QK^T GEMM (bf16): single K-tile (K=64).
// ---------------------------------------------------------------------------
__global__ void __launch_bounds__(256) gemm_qk(
    const __nv_bfloat16* __restrict__ QK, __nv_bfloat16* __restrict__ S)
{
    constexpr int SAB = 72;
    constexpr int ASTG = 128 * SAB;
    constexpr int LDQ = 2 * DMODEL;
    constexpr int MI = 2, NI = 8;

    extern __shared__ __nv_bfloat16 smem_b[];
    __nv_bfloat16* As = smem_b;
    __nv_bfloat16* Bs = smem_b + ASTG;

    int z = blockIdx.z;
    int bb = z >> 4, hh = z & 15;
    const __nv_bfloat16* Qb = QK + (size_t)bb * NSEQ * LDQ + hh * DHEAD;
    const __nv_bfloat16* Kb = Qb + DMODEL;
    __nv_bfloat16* Sb = S + (size_t)z * NSEQ * NSEQ;

    int m0 = blockIdx.y * 128;
    int n0 = blockIdx.x * 128;

    int t = threadIdx.x;
    int lane = t & 31, wid = t >> 5;
    int g = lane >> 2, q4 = lane & 3;
    int wm0 = (wid & 3) * 32;
    int wn0 = (wid >> 2) * 64;

    #pragma unroll
    for (int i = 0; i < 4; i++) {
        int c = i * 256 + t;
        int row = c >> 3, ch = (c & 7) * 8;
        cpa16(As + row * SAB + ch, Qb + (size_t)(m0 + row) * LDQ + ch);
    }
    #pragma unroll
    for (int i = 0; i < 4; i++) {
        int c = i * 256 + t;
        int row = c >> 3, ch = (c & 7) * 8;
        cpa16(Bs + row * SAB + ch, Kb + (size_t)(n0 + row) * LDQ + ch);
    }
    asm volatile("cp.async.commit_group;");
    asm volatile("cp.async.wait_group 0;");
    __syncthreads();

    float acc[MI][NI][4];
    #pragma unroll
    for (int mi = 0; mi < MI; mi++)
        #pragma unroll
        for (int ni = 0; ni < NI; ni++)
            #pragma unroll
            for (int rr = 0; rr < 4; rr++) acc[mi][ni][rr] = 0.f;

    const unsigned* Ag = (const unsigned*)As;
    const unsigned* Bg = (const unsigned*)Bs;
    #pragma unroll
    for (int ks = 0; ks < 4; ks++) {
        unsigned a[MI][4];
        #pragma unroll
        for (int mi = 0; mi < MI; mi++) {
            int row = wm0 + mi * 16 + g;
            const unsigned* p  = Ag + row * 36 + ks * 8 + q4;
            const unsigned* p8 = Ag + (row + 8) * 36 + ks * 8 + q4;
            a[mi][0] = p[0];
            a[mi][1] = p8[0];
            a[mi][2] = p[4];
            a[mi][3] = p8[4];
        }
        unsigned b[NI][2];
        #pragma unroll
        for (int ni = 0; ni < NI; ni++) {
            const unsigned* p = Bg + (wn0 + ni * 8 + g) * 36 + ks * 8 + q4;
            b[ni][0] = p[0];
            b[ni][1] = p[4];
        }
        #pragma unroll
        for (int mi = 0; mi < MI; mi++)
            #pragma unroll
            for (int ni = 0; ni < NI; ni++)
                mma16bf(acc[mi][ni], a[mi], b[ni]);
    }

    #pragma unroll
    for (int mi = 0; mi < MI; mi++) {
        int r0 = m0 + wm0 + mi * 16 + g;
        #pragma unroll
        for (int ni = 0; ni < NI; ni++) {
            int cb = n0 + wn0 + ni * 8 + 2 * q4;
            float* a4 = acc[mi][ni];
            *(__nv_bfloat162*)(Sb + (size_t)r0 * NSEQ + cb) =
                __floats2bfloat162_rn(a4[0] * 0.125f, a4[1] * 0.125f);
            *(__nv_bfloat162*)(Sb + (size_t)(r0 + 8) * NSEQ + cb) =
                __floats2bfloat162_rn(a4[2] * 0.125f, a4[3] * 0.125f);
        }
    }
}

// ---------------------------------------------------------------------------
// P@V GEMM (bf16): O bf16 head-interleaved [b][i][h*64+d].
// ---------------------------------------------------------------------------
__global__ void __launch_bounds__(256, 2) gemm_pv(
    const __nv_bfloat16* __restrict__ P, const __nv_bfloat16* __restrict__ VT,
    __nv_bfloat16* __restrict__ O)
{
    constexpr int SAB = 72;
    constexpr int ASTG = 128 * SAB;
    constexpr int BSTG = 64 * SAB;
    constexpr int MI = 2, NI = 4;

    extern __shared__ __nv_bfloat16 smem_b[];
    __nv_bfloat16* As = smem_b;
    __nv_bfloat16* Bs = smem_b + 2 * ASTG;

    int z = blockIdx.z;
    int bb = z >> 4, hh = z & 15;
    const __nv_bfloat16* Pb = P + (size_t)z * NSEQ * NSEQ;
    const __nv_bfloat16* Vt = VT + (size_t)z * DHEAD * NSEQ;
    __nv_bfloat16* Ob = O + (size_t)bb * NSEQ * DMODEL + hh * DHEAD;

    int m0 = blockIdx.y * 128;
    int t = threadIdx.x, lane = t & 31, wid = t >> 5;
    int g = lane >> 2, q4 = lane & 3;
    int wm0 = (wid & 3) * 32;
    int wn0 = (wid >> 2) * 32;

    float acc[MI][NI][4];
    #pragma unroll
    for (int mi = 0; mi < MI; mi++)
        #pragma unroll
        for (int ni = 0; ni < NI; ni++)
            #pragma unroll
            for (int rr = 0; rr < 4; rr++) acc[mi][ni][rr] = 0.f;

    auto issue = [&](int s, int kt) {
        __nv_bfloat16* Ad = As + s * ASTG;
        __nv_bfloat16* Bd = Bs + s * BSTG;
        const __nv_bfloat16* Asrc = Pb + kt * 64;
        const __nv_bfloat16* Bsrc = Vt + kt * 64;
        #pragma unroll
        for (int i2 = 0; i2 < 4; i2++) {
            int c = i2 * 256 + t;
            int row = c >> 3, ch = (c & 7) * 8;
            cpa16(Ad + row * SAB + ch, Asrc + (size_t)(m0 + row) * NSEQ + ch);
        }
        #pragma unroll
        for (int i2 = 0; i2 < 2; i2++) {
            int c = i2 * 256 + t;
            int row = c >> 3, ch = (c & 7) * 8;
            cpa16(Bd + row * SAB + ch, Bsrc + (size_t)row * NSEQ + ch);
        }
        asm volatile("cp.async.commit_group;");
    };

    auto compute = [&](int s) {
        const unsigned* Ag = (const unsigned*)(As + s * ASTG);
        const unsigned* Bg = (const unsigned*)(Bs + s * BSTG);
        #pragma unroll
        for (int ks = 0; ks < 4; ks++) {
            unsigned a[MI][4];
            #pragma unroll
            for (int mi = 0; mi < MI; mi++) {
                int row = wm0 + mi * 16 + g;
                const unsigned* p  = Ag + row * 36 + ks * 8 + q4;
                const unsigned* p8 = Ag + (row + 8) * 36 + ks * 8 + q4;
                a[mi][0] = p[0];
                a[mi][1] = p8[0];
                a[mi][2] = p[4];
                a[mi][3] = p8[4];
            }
            unsigned b[NI][2];
            #pragma unroll
            for (int ni = 0; ni < NI; ni++) {
                const unsigned* p = Bg + (wn0 + ni * 8 + g) * 36 + ks * 8 + q4;
                b[ni][0] = p[0];
                b[ni][1] = p[4];
            }
            #pragma unroll
            for (int mi = 0; mi < MI; mi++)
                #pragma unroll
                for (int ni = 0; ni < NI; ni++)
                    mma16bf(acc[mi][ni], a[mi], b[ni]);
        }
    };

    int KT = NSEQ / 64;   // 16
    issue(0, 0);
    for (int kt = 0; kt < KT; kt++) {
        if (kt + 1 < KT) {
            issue((kt + 1) & 1, kt + 1);
            asm volatile("cp.async.wait_group 1;");
        } else {
            asm volatile("cp.async.wait_group 0;");
        }
        __syncthreads();
        compute(kt & 1);
        __syncthreads();
    }

    #pragma unroll
    for (int mi = 0; mi < MI; mi++) {
        int r0 = m0 + wm0 + mi * 16 + g;
        #pragma unroll
        for (int ni = 0; ni < NI; ni++) {
            int cb = wn0 + ni * 8 + 2 * q4;
            float* a4 = acc[mi][ni];
            *(__nv_bfloat162*)(Ob + (size_t)r0 * DMODEL + cb) =
                __floats2bfloat162_rn(a4[0], a4[1]);
            *(__nv_bfloat162*)(Ob + (size_t)(r0 + 8) * DMODEL + cb) =
                __floats2bfloat162_rn(a4[2], a4[3]);
        }
    }
}

// ---------------------------------------------------------------------------
// BF16 out-proj GEMM: out = x + gamma1 * (obuf @ out_w^T + out_b)
// ---------------------------------------------------------------------------
__global__ void __launch_bounds__(256, 2) gemm_obf(
    const __nv_bfloat16* __restrict__ A, const __nv_bfloat16* __restrict__ W,
    const float* __restrict__ bias, float* __restrict__ C,
    const float* __restrict__ res, const float* __restrict__ gamma)
{
    constexpr int BM = 128, BK = 64;
    constexpr int SAB = 72;
    constexpr int ASTG = BM * SAB;
    constexpr int MI = 2, NI = 8;
    const int lda = DMODEL, ldb = DMODEL, ldc = DMODEL;

    extern __shared__ __nv_bfloat16 smem_b[];
    __nv_bfloat16* As = smem_b;
    __nv_bfloat16* Bs = smem_b + 2 * ASTG;

    int m0 = blockIdx.y * BM;
    int n0 = blockIdx.x * 128;

    int t = threadIdx.x;
    int lane = t & 31, wid = t >> 5;
    int g = lane >> 2, q4 = lane & 3;
    int wm0 = (wid & 3) * 32;
    int wn0 = (wid >> 2) * 64;

    float acc[MI][NI][4];
    #pragma unroll
    for (int mi = 0; mi < MI; mi++)
        #pragma unroll
        for (int ni = 0; ni < NI; ni++)
            #pragma unroll
            for (int rr = 0; rr < 4; rr++) acc[mi][ni][rr] = 0.f;

    const __nv_bfloat16* Abase = A + (size_t)m0 * lda;
    const __nv_bfloat16* Bbase = W + (size_t)n0 * ldb;

    auto issue = [&](int stage, int kt) {
        __nv_bfloat16* Ad = As + stage * ASTG;
        __nv_bfloat16* Bd = Bs + stage * ASTG;
        const __nv_bfloat16* Asrc = Abase + kt * BK;
        const __nv_bfloat16* Bsrc = Bbase + kt * BK;
        #pragma unroll
        for (int i2 = 0; i2 < 4; i2++) {
            int c = i2 * 256 + t;
            int row = c >> 3, ch = (c & 7) * 8;
            cpa16(Ad + row * SAB + ch, Asrc + (size_t)row * lda + ch);
        }
        #pragma unroll
        for (int i2 = 0; i2 < 4; i2++) {
            int c = i2 * 256 + t;
            int row = c >> 3, ch = (c & 7) * 8;
            cpa16(Bd + row * SAB + ch, Bsrc + (size_t)row * ldb + ch);
        }
        asm volatile("cp.async.commit_group;");
    };

    auto compute = [&](int stage) {
        const unsigned* Ag = (const unsigned*)(As + stage * ASTG);
        const unsigned* Bg = (const unsigned*)(Bs + stage * ASTG);
        #pragma unroll
        for (int ks = 0; ks < 4; ks++) {
            unsigned a[MI][4];
            #pragma unroll
            for (int mi = 0; mi < MI; mi++) {
                int row = wm0 + mi * 16 + g;
                const unsigned* p  = Ag + row * 36 + ks * 8 + q4;
                const unsigned* p8 = Ag + (row + 8) * 36 + ks * 8 + q4;
                a[mi][0] = p[0];
                a[mi][1] = p8[0];
                a[mi][2] = p[4];
                a[mi][3] = p8[4];
            }
            unsigned b[NI][2];
            #pragma unroll
            for (int ni = 0; ni < NI; ni++) {
                const unsigned* p = Bg + (wn0 + ni * 8 + g) * 36 + ks * 8 + q4;
                b[ni][0] = p[0];
                b[ni][1] = p[4];
            }
            #pragma unroll
            for (int mi = 0; mi < MI; mi++)
                #pragma unroll
                for (int ni = 0; ni < NI; ni++)
                    mma16bf(acc[mi][ni], a[mi], b[ni]);
        }
    };

    int KT = DMODEL / BK;   // 16
    issue(0, 0);
    for (int kt = 0; kt < KT; kt++) {
        if (kt + 1 < KT) {
            issue((kt + 1) & 1, kt + 1);
            asm volatile("cp.async.wait_group 1;");
        } else {
            asm volatile("cp.async.wait_group 0;");
        }
        __syncthreads();
        compute(kt & 1);
        __syncthreads();
    }

    #pragma unroll
    for (int mi = 0; mi < MI; mi++) {
        int r0 = m0 + wm0 + mi * 16 + g;
        #pragma unroll
        for (int ni = 0; ni < NI; ni++) {
            int cb = n0 + wn0 + ni * 8 + 2 * q4;
            float2 b2 = *(const float2*)(bias + cb);
            float2 g2 = *(const float2*)(gamma + cb);
            float* a4 = acc[mi][ni];
            float2 rA = *(const float2*)(res + (size_t)r0 * ldc + cb);
            float2 rB = *(const float2*)(res + (size_t)(r0 + 8) * ldc + cb);
            float v0 = rA.x + g2.x * (a4[0] + b2.x);
            float v1 = rA.y + g2.y * (a4[1] + b2.y);
            float v2 = rB.x + g2.x * (a4[2] + b2.x);
            float v3 = rB.y + g2.y * (a4[3] + b2.y);
            *(float2*)(C + (size_t)r0 * ldc + cb)       = make_float2(v0, v1);
            *(float2*)(C + (size_t)(r0 + 8) * ldc + cb) = make_float2(v2, v3);
        }
    }
}

// ---------------------------------------------------------------------------
// FP16 FFN GEMM: C = epi(A @ W^T + bias).  A/W fp16, fp32 accumulate.
//   EPI 2: gelu -> fp16 out (fc1).  EPI 3: res + gamma*(.) -> fp32 out (fc2).
//   Tile 128x128x64, m16n8k16.f16, 2-stage (same proven structure).
// ---------------------------------------------------------------------------
template <int EPI>
__global__ void __launch_bounds__(256, 2) gemm_ff(
    const __half* __restrict__ A, const __half* __restrict__ W,
    const float* __restrict__ bias, void* __restrict__ Cout,
    const float* __restrict__ res, const float* __restrict__ gamma,
    int K, int lda, int ldb, int ldc)
{
    constexpr int BM = 128, BK = 64;
    constexpr int SAB = 72;
    constexpr int ASTG = BM * SAB;
    constexpr int MI = 2, NI = 8;

    extern __shared__ __half smem_h[];
    __half* As = smem_h;
    __half* Bs = smem_h + 2 * ASTG;

    int m0 = blockIdx.y * BM;
    int n0 = blockIdx.x * 128;

    int t = threadIdx.x;
    int lane = t & 31, wid = t >> 5;
    int g = lane >> 2, q4 = lane & 3;
    int wm0 = (wid & 3) * 32;
    int wn0 = (wid >> 2) * 64;

    float acc[MI][NI][4];
    #pragma unroll
    for (int mi = 0; mi < MI; mi++)
        #pragma unroll
        for (int ni = 0; ni < NI; ni++)
            #pragma unroll
            for (int rr = 0; rr < 4; rr++) acc[mi][ni][rr] = 0.f;

    const __half* Abase = A + (size_t)m0 * lda;
    const __half* Bbase = W + (size_t)n0 * ldb;

    auto issue = [&](int stage, int kt) {
        __half* Ad = As + stage * ASTG;
        __half* Bd = Bs + stage * ASTG;
        const __half* Asrc = Abase + kt * BK;
        const __half* Bsrc = Bbase + kt * BK;
        #pragma unroll
        for (int i2 = 0; i2 < 4; i2++) {
            int c = i2 * 256 + t;
            int row = c >> 3, ch = (c & 7) * 8;
            cpa16(Ad + row * SAB + ch, Asrc + (size_t)row * lda + ch);
        }
        #pragma unroll
        for (int i2 = 0; i2 < 4; i2++) {
            int c = i2 * 256 + t;
            int row = c >> 3, ch = (c & 7) * 8;
            cpa16(Bd + row * SAB + ch, Bsrc + (size_t)row * ldb + ch);
        }
        asm volatile("cp.async.commit_group;");
    };

    auto compute = [&](int stage) {
        const unsigned* Ag = (const unsigned*)(As + stage * ASTG);
        const unsigned* Bg = (const unsigned*)(Bs + stage * ASTG);
        #pragma unroll
        for (int ks = 0; ks < 4; ks++) {
            unsigned a[MI][4];
            #pragma unroll
            for (int mi = 0; mi < MI; mi++) {
                int row = wm0 + mi * 16 + g;
                const unsigned* p  = Ag + row * 36 + ks * 8 + q4;
                const unsigned* p8 = Ag + (row + 8) * 36 + ks * 8 + q4;
                a[mi][0] = p[0];
                a[mi][1] = p8[0];
                a[mi][2] = p[4];
                a[mi][3] = p8[4];
            }
            unsigned b[NI][2];
            #pragma unroll
            for (int ni = 0; ni < NI; ni++) {
                const unsigned* p = Bg + (wn0 + ni * 8 + g) * 36 + ks * 8 + q4;
                b[ni][0] = p[0];
                b[ni][1] = p[4];
            }
            #pragma unroll
            for (int mi = 0; mi < MI; mi++)
                #pragma unroll
                for (int ni = 0; ni < NI; ni++)
                    mma16h(acc[mi][ni], a[mi], b[ni]);
        }
    };

    int KT = K / BK;
    issue(0, 0);
    for (int kt = 0; kt < KT; kt++) {
        if (kt + 1 < KT) {
            issue((kt + 1) & 1, kt + 1);
            asm volatile("cp.async.wait_group 1;");
        } else {
            asm volatile("cp.async.wait_group 0;");
        }
        __syncthreads();
        compute(kt & 1);
        __syncthreads();
    }

    #pragma unroll
    for (int mi = 0; mi < MI; mi++) {
        int r0 = m0 + wm0 + mi * 16 + g;
        #pragma unroll
        for (int ni = 0; ni < NI; ni++) {
            int cb = n0 + wn0 + ni * 8 + 2 * q4;
            float2 b2 = *(const float2*)(bias + cb);
            float* a4 = acc[mi][ni];
            float v0 = a4[0] + b2.x, v1 = a4[1] + b2.y;
            float v2 = a4[2] + b2.x, v3 = a4[3] + b2.y;
            if (EPI == 2) {
                v0 = gelu_tanh(v0); v1 = gelu_tanh(v1);
                v2 = gelu_tanh(v2); v3 = gelu_tanh(v3);
                __half* Ch = (__half*)Cout;
                *(__half2*)(Ch + (size_t)r0 * ldc + cb)       = __floats2half2_rn(v0, v1);
                *(__half2*)(Ch + (size_t)(r0 + 8) * ldc + cb) = __floats2half2_rn(v2, v3);
            } else {
                float2 g2 = *(const float2*)(gamma + cb);
                float2 rA = *(const float2*)(res + (size_t)r0 * ldc + cb);
                float2 rB = *(const float2*)(res + (size_t)(r0 + 8) * ldc + cb);
                v0 = rA.x + g2.x * v0; v1 = rA.y + g2.y * v1;
                v2 = rB.x + g2.x * v2; v3 = rB.y + g2.y * v3;
                float* Cf = (float*)Cout;
                *(float2*)(Cf + (size_t)r0 * ldc + cb)       = make_float2(v0, v1);
                *(float2*)(Cf + (size_t)(r0 + 8) * ldc + cb) = make_float2(v2, v3);
            }
        }
    }
}

// ---------------------------------------------------------------------------
// Fused talking-heads: mix -> softmax -> mix, in place on S (bf16 I/O).
// ---------------------------------------------------------------------------
__global__ void __launch_bounds__(512) attn_mix_softmax(
    const float* __restrict__ wl, const float* __restrict__ bl,
    const float* __restrict__ ww, const float* __restrict__ bw,
    __nv_bfloat16* __restrict__ S)
{
    extern __shared__ float Ssh[];      // [16][1024] fp32
    __shared__ float wls[256], wws[256], bls[16], bws[16];

    int t = threadIdx.x;
    int b = blockIdx.x >> 10;
    int i = blockIdx.x & 1023;

    if (t < 256) { wls[t] = wl[t]; wws[t] = ww[t]; }
    if (t < 16)  { bls[t] = bl[t]; bws[t] = bw[t]; }

    __nv_bfloat16* Sg = S + (size_t)(b * NHEAD) * NSEQ * NSEQ + (size_t)i * NSEQ;
    const long long NN = (long long)NSEQ * NSEQ;

    #pragma unroll
    for (int ii = 0; ii < 4; ii++) {
        int idx = ii * 512 + t;
        int h = idx >> 7, j4 = idx & 127;
        uint4 raw = ((const uint4*)(Sg + (size_t)h * NN))[j4];
        float* dst = Ssh + h * NSEQ + j4 * 8;
        unsigned p0 = raw.x, p1 = raw.y, p2 = raw.z, p3 = raw.w;
        dst[0] = __uint_as_float(p0 << 16); dst[1] = __uint_as_float(p0 & 0xFFFF0000u);
        dst[2] = __uint_as_float(p1 << 16); dst[3] = __uint_as_float(p1 & 0xFFFF0000u);
        dst[4] = __uint_as_float(p2 << 16); dst[5] = __uint_as_float(p2 & 0xFFFF0000u);
        dst[6] = __uint_as_float(p3 << 16); dst[7] = __uint_as_float(p3 & 0xFFFF0000u);
    }
    __syncthreads();

    #pragma unroll
    for (int jj = 0; jj < 2; jj++) {
        int j = t + jj * 512;
        float sv[16];
        #pragma unroll
        for (int h = 0; h < 16; h++) sv[h] = Ssh[h * NSEQ + j];
        #pragma unroll
        for (int gg = 0; gg < 16; gg++) {
            float acc = bls[gg];
            #pragma unroll
            for (int h = 0; h < 16; h++) acc += wls[gg * 16 + h] * sv[h];
            Ssh[gg * NSEQ + j] = acc;
        }
    }
    __syncthreads();

    {
        int w = t >> 5, l = t & 31;
        float* row = Ssh + w * NSEQ;
        float mx = -1e30f;
        for (int m = l; m < NSEQ; m += 32) mx = fmaxf(mx, row[m]);
        #pragma unroll
        for (int o = 16; o; o >>= 1) mx = fmaxf(mx, __shfl_xor_sync(0xffffffffu, mx, o));
        float sum = 0.f;
        for (int m = l; m < NSEQ; m += 32) {
            float e = __expf(row[m] - mx);
            row[m] = e;
            sum += e;
        }
        #pragma unroll
        for (int o = 16; o; o >>= 1) sum += __shfl_xor_sync(0xffffffffu, sum, o);
        float inv = 1.f / sum;
        for (int m = l; m < NSEQ; m += 32) row[m] *= inv;
    }
    __syncthreads();

    #pragma unroll
    for (int jj = 0; jj < 2; jj++) {
        int j = t + jj * 512;
        float pv[16];
        #pragma unroll
        for (int h = 0; h < 16; h++) pv[h] = Ssh[h * NSEQ + j];
        #pragma unroll
        for (int gg = 0; gg < 16; gg++) {
            float acc = bws[gg];
            #pragma unroll
            for (int h = 0; h < 16; h++) acc += wws[gg * 16 + h] * pv[h];
            Ssh[gg * NSEQ + j] = acc;
        }
    }
    __syncthreads();

    #pragma unroll
    for (int ii = 0; ii < 4; ii++) {
        int idx = ii * 512 + t;
        int h = idx >> 7, j4 = idx & 127;
        const float* src = Ssh + h * NSEQ + j4 * 8;
        uint4 raw;
        __nv_bfloat162 h0 = __floats2bfloat162_rn(src[0], src[1]);
        __nv_bfloat162 h1 = __floats2bfloat162_rn(src[2], src[3]);
        __nv_bfloat162 h2 = __floats2bfloat162_rn(src[4], src[5]);
        __nv_bfloat162 h3 = __floats2bfloat162_rn(src[6], src[7]);
        raw.x = *(unsigned*)&h0; raw.y = *(unsigned*)&h1;
        raw.z = *(unsigned*)&h2; raw.w = *(unsigned*)&h3;
        ((uint4*)(Sg + (size_t)h * NN))[j4] = raw;
    }
}

// ---------------------------------------------------------------------------
// Launch
// ---------------------------------------------------------------------------
extern "C" void kernel_launch(void* const* d_in, const int* in_sizes, int n_in,
                              void* d_out, int out_size)
{
    const float* x      = (const float*)d_in[0];
    const float* ln1_w  = (const float*)d_in[1];
    const float* ln1_b  = (const float*)d_in[2];
    const float* qkv_w  = (const float*)d_in[3];
    const float* qkv_b  = (const float*)d_in[4];
    const float* pl_w   = (const float*)d_in[5];
    const float* pl_b   = (const float*)d_in[6];
    const float* pw_w   = (const float*)d_in[7];
    const float* pw_b   = (const float*)d_in[8];
    const float* out_w  = (const float*)d_in[9];
    const float* out_b  = (const float*)d_in[10];
    const float* gamma1 = (const float*)d_in[11];
    const float* ln2_w  = (const float*)d_in[12];
    const float* ln2_b  = (const float*)d_in[13];
    const float* fc1_w  = (const float*)d_in[14];
    const float* fc1_b  = (const float*)d_in[15];
    const float* fc2_w  = (const float*)d_in[16];
    const float* fc2_b  = (const float*)d_in[17];
    const float* gamma2 = (const float*)d_in[18];
    float* out = (float*)d_out;

    float *hbuf, *vbuf, *obuf, *ff, *wq, *wo, *wf1, *wf2;
    __nv_bfloat16 *S, *qk;
    cudaGetSymbolAddress((void**)&hbuf, g_h);
    cudaGetSymbolAddress((void**)&vbuf, g_v);
    cudaGetSymbolAddress((void**)&qk,   g_qk);
    cudaGetSymbolAddress((void**)&S,    g_S);
    cudaGetSymbolAddress((void**)&obuf, g_o);
    cudaGetSymbolAddress((void**)&ff,   g_ff);
    cudaGetSymbolAddress((void**)&wq,   g_wq);
    cudaGetSymbolAddress((void**)&wo,   g_wo);
    cudaGetSymbolAddress((void**)&wf1,  g_wf1);
    cudaGetSymbolAddress((void**)&wf2,  g_wf2);

    __nv_bfloat16* hb   = (__nv_bfloat16*)hbuf;   // LN1 bf16 alias
    __half*        hh   = (__half*)hbuf;          // LN2 fp16 alias
    __nv_bfloat16* wqb  = (__nv_bfloat16*)wq;
    __nv_bfloat16* wob  = (__nv_bfloat16*)wo;
    __half*        wf1h = (__half*)wf1;
    __half*        wf2h = (__half*)wf2;
    __nv_bfloat16* vt   = (__nv_bfloat16*)vbuf;
    __nv_bfloat16* ob   = (__nv_bfloat16*)obuf;
    __half*        ffh  = (__half*)ff;

    const int BF_SMEM = 4 * 128 * 72 * 2;                 // 73728 B
    const int QK_SMEM = 2 * 128 * 72 * 2;                 // 36864 B
    const int PV_SMEM = (2 * 128 * 72 + 2 * 64 * 72) * 2; // 55296 B

    cudaFuncSetAttribute(attn_mix_softmax,
                         cudaFuncAttributeMaxDynamicSharedMemorySize, 65536);
    cudaFuncSetAttribute(gemm_qkv_bf, cudaFuncAttributeMaxDynamicSharedMemorySize, BF_SMEM);
    cudaFuncSetAttribute(gemm_obf, cudaFuncAttributeMaxDynamicSharedMemorySize, BF_SMEM);
    cudaFuncSetAttribute(gemm_qk, cudaFuncAttributeMaxDynamicSharedMemorySize, QK_SMEM);
    cudaFuncSetAttribute(gemm_pv, cudaFuncAttributeMaxDynamicSharedMemorySize, PV_SMEM);
    cudaFuncSetAttribute(gemm_ff<2>, cudaFuncAttributeMaxDynamicSharedMemorySize, BF_SMEM);
    cudaFuncSetAttribute(gemm_ff<3>, cudaFuncAttributeMaxDynamicSharedMemorySize, BF_SMEM);

    // 0) Weight prep: qkv,out_w -> bf16; fc1,fc2 -> fp16
    prep_w<<<dim3(1024, 4), 256>>>(
        qkv_w, wqb,  3 * DMODEL * DMODEL / 4,
        out_w, wob,  DMODEL * DMODEL / 4,
        fc1_w, wf1h, FFDIM * DMODEL / 4,
        fc2_w, wf2h, FFDIM * DMODEL / 4);

    // 1) LN1 -> bf16
    ln_kernel<1><<<MROWS, 256>>>(x, ln1_w, ln1_b, hb);

    // 2) qkv (bf16), split epilogue: Q,K -> g_qk; V -> V^T bf16
    gemm_qkv_bf<<<dim3(24, 32), 256, BF_SMEM>>>(hb, wqb, qkv_b, qk, vt);

    // 3) S = (Q K^T)/8
    gemm_qk<<<dim3(8, 8, 64), 256, QK_SMEM>>>(qk, S);

    // 4) talking-heads mix -> softmax -> mix
    attn_mix_softmax<<<BSZ * NSEQ, 512, 65536>>>(pl_w, pl_b, pw_w, pw_b, S);

    // 5) O = P2 @ V  (bf16 out)
    gemm_pv<<<dim3(1, 8, 64), 256, PV_SMEM>>>(S, vt, ob);

    // 6) x1 = x + gamma1 * (O @ out_w^T + out_b)
    gemm_obf<<<dim3(8, 32), 256, BF_SMEM>>>(ob, wob, out_b, out, x, gamma1);

    // 7) LN2 -> fp16
    ln_kernel<2><<<MROWS, 256>>>(out, ln2_w, ln2_b, hh);

    // 8) ff = gelu(hh @ fc1_w^T + fc1_b)   (fp16, fp16 out)
    gemm_ff<2><<<dim3(32, 32), 256, BF_SMEM>>>(
        hh, wf1h, fc1_b, ffh, nullptr, nullptr,
        DMODEL, DMODEL, DMODEL, FFDIM);

    // 9) out = x1 + gamma2 * (ffh @ fc2_w^T + fc2_b)   (fp16, fp32 residual)
    gemm_ff<3><<<dim3(8, 32), 256, BF_SMEM>>>(
        ffh, wf2h, fc2_b, out, out, gamma2,
        FFDIM, FFDIM, FFDIM, DMODEL);
}